// round 4
// baseline (speedup 1.0000x reference)
#include <cuda_runtime.h>
#include <cstdint>
#include <cstddef>

#define BB 2
#define LL 2048
#define HH 16
#define EE 64
#define BS 256
#define NB (LL / BS)                  // 8 blocks
#define OUT_ELEMS (BB * LL * HH * EE) // output tensor precedes attn in d_out

#define QSTRIDE (BS * 16 + 4)         // 4100 floats: 16B skew between quarters
#define SMEM_FLOATS (8 * QSTRIDE)     // K quarters 0..3, V quarters 0..3
typedef unsigned long long ull;

// ---------- packed f32x2 helpers (FFMA2 path, PTX-only) ----------
__device__ __forceinline__ ull pack2(float lo, float hi) {
    ull r;
    asm("mov.b64 %0, {%1, %2};" : "=l"(r) : "f"(lo), "f"(hi));
    return r;
}
__device__ __forceinline__ void unpack2(ull p, float &lo, float &hi) {
    asm("mov.b64 {%0, %1}, %2;" : "=f"(lo), "=f"(hi) : "l"(p));
}
__device__ __forceinline__ void fma2(ull &d, ull a, ull b) {
    asm("fma.rn.f32x2 %0, %1, %2, %0;" : "+l"(d) : "l"(a), "l"(b));
}
__device__ __forceinline__ void add2(ull &d, ull a) {
    asm("add.rn.f32x2 %0, %0, %1;" : "+l"(d) : "l"(a));
}

extern __shared__ float smem[];

__global__ void __launch_bounds__(512, 1)
sparse_attn_kernel(const float *__restrict__ Q,
                   const float *__restrict__ K,
                   const float *__restrict__ V,
                   float *__restrict__ out) {
    const int tid = threadIdx.x;
    const int bid = blockIdx.x;
    const int blk = bid & (NB - 1);
    const int h   = (bid / NB) & (HH - 1);
    const int b   = bid / (NB * HH);

    const int p    = tid & 3;   // E-quarter this thread owns
    const int rp   = tid >> 2;  // row-pair index (0..127)
    const int row0 = rp * 2;    // local query rows row0, row0+1
    const int hsel = p >> 1;    // which half of the 8-key chunk this lane stores
    const int rsel = p & 1;     // which of the 2 rows this lane stores/normalizes

    // ---- stage K,V block into quarter-split, skewed smem ----
    // quarter qt of key row j lives at smem[qt*QSTRIDE + j*16] (+4*QSTRIDE for V)
    {
        #pragma unroll
        for (int i = 0; i < 8; i++) {
            int idx = i * 512 + tid;       // 4096 float4 per tensor
            int row = idx >> 4;
            int c4  = idx & 15;
            int qt  = c4 >> 2;
            int cc  = (c4 & 3) * 4;
            size_t g = (((size_t)b * LL + blk * BS + row) * HH + h) * EE + c4 * 4;
            *(float4 *)(smem + qt * QSTRIDE + row * 16 + cc) =
                *(const float4 *)(K + g);
            *(float4 *)(smem + 4 * QSTRIDE + qt * QSTRIDE + row * 16 + cc) =
                *(const float4 *)(V + g);
        }
    }
    __syncthreads();

    const float *sKq = smem + p * QSTRIDE;
    const float *sVq = smem + 4 * QSTRIDE + p * QSTRIDE;

    // ---- load both query rows' quarter into packed registers ----
    ull q0[8], q1[8];
    {
        const ulonglong2 *qp0 =
            (const ulonglong2 *)(Q + (((size_t)b * LL + blk * BS + row0) * HH + h) * EE + p * 16);
        const ulonglong2 *qp1 =
            (const ulonglong2 *)(Q + (((size_t)b * LL + blk * BS + row0 + 1) * HH + h) * EE + p * 16);
        #pragma unroll
        for (int i = 0; i < 4; i++) {
            ulonglong2 t0 = qp0[i];
            ulonglong2 t1 = qp1[i];
            q0[2 * i] = t0.x; q0[2 * i + 1] = t0.y;
            q1[2 * i] = t1.x; q1[2 * i + 1] = t1.y;
        }
    }

    ull o0[8], o1[8];
    #pragma unroll
    for (int i = 0; i < 8; i++) { o0[i] = 0ULL; o1[i] = 0ULL; }
    float lsum0 = 0.f, lsum1 = 0.f;

    // attn tensor layout [B,H,L,S], after output tensor
    const size_t abase = (size_t)OUT_ELEMS + (size_t)(b * HH + h) * LL * LL;
    float *attn_mine = out + abase + (size_t)(blk * BS + row0 + rsel) * LL + (size_t)blk * BS;
    float *attn_cta  = out + abase + (size_t)(blk * BS) * LL;

    const int blk64 = blk * 64;

    // ---- main loop: 32 chunks x 8 keys, zeros interleaved ----
    for (int ch = 0; ch < 32; ch++) {
        float eb[8]; // e values of this lane's assigned row for the chunk
        #pragma unroll
        for (int jj = 0; jj < 8; jj++) {
            const int j = ch * 8 + jj;
            const ulonglong2 *kp = (const ulonglong2 *)(sKq + j * 16);
            ull a00 = 0, a01 = 0, a10 = 0, a11 = 0;
            #pragma unroll
            for (int i = 0; i < 4; i++) {
                ulonglong2 kk = kp[i];
                fma2(a00, q0[2 * i],     kk.x);
                fma2(a01, q0[2 * i + 1], kk.y);
                fma2(a10, q1[2 * i],     kk.x);
                fma2(a11, q1[2 * i + 1], kk.y);
            }
            add2(a00, a01);
            add2(a10, a11);
            float l0, h0, l1, h1;
            unpack2(a00, l0, h0);
            unpack2(a10, l1, h1);
            float s0 = l0 + h0;   // quarter-partial dots
            float s1 = l1 + h1;
            // 4-lane butterfly (commutative adds -> identical across lanes)
            s0 += __shfl_xor_sync(0xffffffffu, s0, 1);
            s1 += __shfl_xor_sync(0xffffffffu, s1, 1);
            s0 += __shfl_xor_sync(0xffffffffu, s0, 2);
            s1 += __shfl_xor_sync(0xffffffffu, s1, 2);
            float e0 = __expf(s0);  // no-max softmax: |s| bounded, fp32-safe
            float e1 = __expf(s1);
            lsum0 += e0;
            lsum1 += e1;
            eb[jj] = rsel ? e1 : e0;
            ull e0v = pack2(e0, e0);
            ull e1v = pack2(e1, e1);
            const ulonglong2 *vp = (const ulonglong2 *)(sVq + j * 16);
            #pragma unroll
            for (int i = 0; i < 4; i++) {
                ulonglong2 vv = vp[i];
                fma2(o0[2 * i],     vv.x, e0v);
                fma2(o0[2 * i + 1], vv.y, e0v);
                fma2(o1[2 * i],     vv.x, e1v);
                fma2(o1[2 * i + 1], vv.y, e1v);
            }
        }
        // diag e-store: lane covers (row rsel, half hsel) of the chunk
        *(float4 *)(attn_mine + ch * 8 + hsel * 4) =
            make_float4(eb[hsel * 4], eb[hsel * 4 + 1], eb[hsel * 4 + 2], eb[hsel * 4 + 3]);

        // interleaved cooperative zero-fill of off-block region
        // 256 rows x 448 f4 = 114688 = 32 chunks x 7 x 512 threads
        {
            const int zbase = ch * 3584 + tid;
            #pragma unroll
            for (int i = 0; i < 7; i++) {
                int idx  = zbase + i * 512;
                int zrow = idx / 448;
                int c4   = idx - zrow * 448;
                c4 = (c4 >= blk64) ? c4 + 64 : c4;
                __stcs((float4 *)(attn_cta + (size_t)zrow * LL + c4 * 4),
                       make_float4(0.f, 0.f, 0.f, 0.f));
            }
        }
    }

    const float recip0 = 1.0f / lsum0;
    const float recip1 = 1.0f / lsum1;

    // ---- write output: 2 rows x this thread's E-quarter ----
    {
        float *op0 = out + (((size_t)b * LL + blk * BS + row0) * HH + h) * EE + p * 16;
        float *op1 = out + (((size_t)b * LL + blk * BS + row0 + 1) * HH + h) * EE + p * 16;
        #pragma unroll
        for (int i = 0; i < 4; i++) {
            float x0, x1, x2, x3;
            unpack2(o0[2 * i],     x0, x1);
            unpack2(o0[2 * i + 1], x2, x3);
            __stcs((float4 *)(op0 + i * 4),
                   make_float4(x0 * recip0, x1 * recip0, x2 * recip0, x3 * recip0));
            unpack2(o1[2 * i],     x0, x1);
            unpack2(o1[2 * i + 1], x2, x3);
            __stcs((float4 *)(op1 + i * 4),
                   make_float4(x0 * recip1, x1 * recip1, x2 * recip1, x3 * recip1));
        }
    }

    // ---- normalize assigned (row, half) of the attn diag block in place (L2-hot) ----
    {
        const float recm = rsel ? recip1 : recip0;
        float4 *ap = (float4 *)(attn_mine + hsel * 128);
        #pragma unroll 8
        for (int i = 0; i < 32; i++) {
            float4 v = ap[i];
            v.x *= recm; v.y *= recm; v.z *= recm; v.w *= recm;
            ap[i] = v;
        }
    }
}

extern "C" void kernel_launch(void *const *d_in, const int *in_sizes, int n_in,
                              void *d_out, int out_size) {
    const float *Q = (const float *)d_in[0];
    const float *K = (const float *)d_in[1];
    const float *V = (const float *)d_in[2];
    float *out = (float *)d_out;

    const int smem_bytes = SMEM_FLOATS * (int)sizeof(float); // 131200
    cudaFuncSetAttribute(sparse_attn_kernel,
                         cudaFuncAttributeMaxDynamicSharedMemorySize, smem_bytes);

    sparse_attn_kernel<<<BB * HH * NB, 512, smem_bytes>>>(Q, K, V, out);
}